// round 6
// baseline (speedup 1.0000x reference)
#include <cuda_runtime.h>
#include <math.h>

// ============================================================================
// ExponentialConcordanceLoss, O(N), 8-CTA cluster, 3 cluster syncs.
//
// loss = ( sum_{i,j: t[j]<t[i], e[j], finite both} exp(s[i]-s[j]) ) / max(cnt,1)
//   a[i]  = finite[i] ? exp(s[i]) : 0
//   b0[j] = (finite[j] && e[j]) ? exp(-s[j]) : 0
//   total = sum_i a[i] * ( prefB0[bucket(i)] + same-bucket strict compares )
//
// Per replay:
//   A: each thread loads ONLY its own element; prep (fin/e/exp); CTA min/max
//      of finite t -> g_blkMin/Max[cta].
//   --- cluster.sync #1 ---
//   B: read the 8 (min,max) pairs, derive identical scale everywhere; bucket;
//      event-only histogram into global hist (zero-invariant across replays:
//      re-zeroed in phase E of the previous replay; zero at module load).
//   --- cluster.sync #2 ---
//   C: per-CTA local exclusive scan of 1024 buckets into SMEM (1 bkt/thread).
//   D: scatter event records (t_j, b0_j) into bucket-sorted g_srec.
//   --- cluster.sync #3 ---
//   E: gather (prefix + short exact same-bucket loop, strict <, drops
//      ties/self), re-zero histogram for next replay, block reduce.
//   F: ticket: LAST block reduces the 8 partials in fixed order
//      (deterministic), writes out, resets ticket.
// Counts int32 end-to-end (max 8192^2 < 2^31).
// ============================================================================

#define NMAX     8192
#define KB       1024
#define NCTAS    8
#define NTHREADS 1024

__device__ int      g_histCnt[KB];     // zero at load; re-zeroed every run
__device__ float    g_histB0[KB];
__device__ float2   g_srec[NMAX];      // bucket-sorted (t, b0) of events
__device__ float    g_blkMin[NCTAS];
__device__ float    g_blkMax[NCTAS];
__device__ float    g_blockSum[NCTAS];
__device__ int      g_blockCnt[NCTAS];
__device__ unsigned g_ticket;          // zero at load; reset by last block

__device__ __forceinline__ void cluster_sync_fenced() {
    __threadfence();
    asm volatile("barrier.cluster.arrive.aligned;" ::: "memory");
    asm volatile("barrier.cluster.wait.aligned;"   ::: "memory");
}

__global__ void __launch_bounds__(NTHREADS, 1) __cluster_dims__(NCTAS, 1, 1)
fused_cluster3(const float* __restrict__ preds,
               const float* __restrict__ targets,
               float* __restrict__ out, int n) {
    __shared__ float sWmn[32], sWmx[32];
    __shared__ float sWsum[32];
    __shared__ int   sWcnt[32];
    __shared__ float s_pB0[KB];          // exclusive prefix of event b0
    __shared__ int   s_st[KB + 1];       // exclusive prefix of event counts
    __shared__ float sScanB[33];
    __shared__ int   sScanN[33];

    const int tid  = threadIdx.x;
    const int cta  = blockIdx.x;
    const int i    = cta * NTHREADS + tid;
    const int lane = tid & 31;
    const int warp = tid >> 5;

    // ---- Phase A: own element only; prep; CTA min/max ----------------------
    float my_s = 0.0f;
    float my_t = __int_as_float(0x7fc00000);    // qNaN
    float my_ev = 0.0f;
    if (i < n) {
        my_s = __ldg(&preds[i]);
        float2 tg = __ldg(&((const float2*)targets)[i]);
        my_t = tg.x; my_ev = tg.y;
    }
    bool fin = isfinite(my_t) && isfinite(my_s);
    bool e   = fin && (my_ev != 0.0f);
    float b0 = e   ? __expf(-my_s) : 0.0f;
    float a  = fin ? __expf(my_s)  : 0.0f;

    float tmn = fin ? my_t : __int_as_float(0x7f800000);   // +inf
    float tmx = fin ? my_t : __int_as_float(0xff800000);   // -inf
#pragma unroll
    for (int o = 16; o > 0; o >>= 1) {
        tmn = fminf(tmn, __shfl_xor_sync(0xffffffffu, tmn, o));
        tmx = fmaxf(tmx, __shfl_xor_sync(0xffffffffu, tmx, o));
    }
    if (lane == 0) { sWmn[warp] = tmn; sWmx[warp] = tmx; }
    __syncthreads();
    if (warp == 0) {
        float a2 = sWmn[lane], b2 = sWmx[lane];
#pragma unroll
        for (int o = 16; o > 0; o >>= 1) {
            a2 = fminf(a2, __shfl_xor_sync(0xffffffffu, a2, o));
            b2 = fmaxf(b2, __shfl_xor_sync(0xffffffffu, b2, o));
        }
        if (lane == 0) { g_blkMin[cta] = a2; g_blkMax[cta] = b2; }
    }
    cluster_sync_fenced();                                 // sync 1

    // ---- Phase B: global scale; event-only histogram ------------------------
    float gmn = __int_as_float(0x7f800000);
    float gmx = __int_as_float(0xff800000);
#pragma unroll
    for (int b = 0; b < NCTAS; b++) {
        gmn = fminf(gmn, __ldcg(&g_blkMin[b]));
        gmx = fmaxf(gmx, __ldcg(&g_blkMax[b]));
    }
    float range = gmx - gmn;
    float scale = (range > 0.0f) ? ((float)KB / range) : 0.0f;

    int bkt = 0, pos = 0;
    if (fin) {
        float x = (my_t - gmn) * scale;
        bkt = (int)x;
        bkt = max(0, min(KB - 1, bkt));
    }
    if (e) {
        pos = atomicAdd(&g_histCnt[bkt], 1);
        atomicAdd(&g_histB0[bkt], b0);
    }
    cluster_sync_fenced();                                 // sync 2

    // ---- Phase C: per-CTA local exclusive scan (1 bucket / thread) ----------
    float hb = __ldcg(&g_histB0[tid]);
    int   hn = __ldcg(&g_histCnt[tid]);
    {
        float rb = hb; int rn = hn;
#pragma unroll
        for (int o = 1; o < 32; o <<= 1) {
            float vb = __shfl_up_sync(0xffffffffu, rb, o);
            int   vn = __shfl_up_sync(0xffffffffu, rn, o);
            if (lane >= o) { rb += vb; rn += vn; }
        }
        if (lane == 31) { sScanB[warp] = rb; sScanN[warp] = rn; }
        __syncthreads();
        if (warp == 0) {
            float wb = sScanB[lane]; int wn = sScanN[lane];
#pragma unroll
            for (int o = 1; o < 32; o <<= 1) {
                float vb = __shfl_up_sync(0xffffffffu, wb, o);
                int   vn = __shfl_up_sync(0xffffffffu, wn, o);
                if (lane >= o) { wb += vb; wn += vn; }
            }
            sScanB[lane + 1] = wb; sScanN[lane + 1] = wn;
            if (lane == 0) { sScanB[0] = 0.0f; sScanN[0] = 0; }
        }
        __syncthreads();
        float ib  = sScanB[warp] + rb;                     // inclusive
        int   in2 = sScanN[warp] + rn;
        s_pB0[tid] = ib - hb;                              // exclusive
        s_st[tid]  = in2 - hn;
        if (tid == KB - 1) s_st[KB] = in2;
    }
    __syncthreads();

    // ---- Phase D: scatter event records into bucket-sorted order ------------
    if (e) g_srec[s_st[bkt] + pos] = make_float2(my_t, b0);
    cluster_sync_fenced();                                 // sync 3

    // ---- Phase E: gather + re-zero histogram for next replay ----------------
    if (tid < KB / NCTAS) {                                // 128 buckets per CTA
        int h = cta * (KB / NCTAS) + tid;
        g_histCnt[h] = 0;
        g_histB0[h]  = 0.0f;
    }

    float ts = 0.0f;
    int   tc = 0;
    if (fin) {
        float S  = s_pB0[bkt];
        int   st = s_st[bkt];
        int   en = s_st[bkt + 1];
        int   C  = st;
        for (int m = st; m < en; m++) {
            float2 rec;
            asm volatile("ld.global.cg.v2.f32 {%0,%1}, [%2];"
                         : "=f"(rec.x), "=f"(rec.y) : "l"(&g_srec[m]));
            if (rec.x < my_t) { S += rec.y; C += 1; }      // strict: drops ties/self
        }
        ts = a * S;
        tc = C;
    }

    // ---- block reduce -------------------------------------------------------
#pragma unroll
    for (int o = 16; o > 0; o >>= 1) {
        ts += __shfl_xor_sync(0xffffffffu, ts, o);
        tc += __shfl_xor_sync(0xffffffffu, tc, o);
    }
    if (lane == 0) { sWsum[warp] = ts; sWcnt[warp] = tc; }
    __syncthreads();
    if (warp == 0) {
        float s2 = sWsum[lane];
        int   c2 = sWcnt[lane];
#pragma unroll
        for (int o = 16; o > 0; o >>= 1) {
            s2 += __shfl_xor_sync(0xffffffffu, s2, o);
            c2 += __shfl_xor_sync(0xffffffffu, c2, o);
        }
        if (lane == 0) { g_blockSum[cta] = s2; g_blockCnt[cta] = c2; }
    }
    __syncthreads();

    // ---- Phase F: ticket-based final reduce (last block, fixed order) -------
    if (tid == 0) {
        __threadfence();
        unsigned tkt = atomicAdd(&g_ticket, 1u);
        if (tkt == NCTAS - 1) {
            __threadfence();
            float     s3 = 0.0f;
            long long c3 = 0;
#pragma unroll
            for (int b = 0; b < NCTAS; b++) {
                s3 += __ldcg(&g_blockSum[b]);
                c3 += (long long)__ldcg(&g_blockCnt[b]);
            }
            out[0] = s3 / fmaxf((float)c3, 1.0f);
            atomicExch(&g_ticket, 0u);                     // reset for next replay
        }
    }
}

// ---------------------------------------------------------------------------
extern "C" void kernel_launch(void* const* d_in, const int* in_sizes, int n_in,
                              void* d_out, int out_size) {
    const float* preds   = (const float*)d_in[0];
    const float* targets = (const float*)d_in[1];
    int n = in_sizes[0];
    if (n > NMAX) n = NMAX;
    fused_cluster3<<<NCTAS, NTHREADS>>>(preds, targets, (float*)d_out, n);
}

// round 7
// speedup vs baseline: 1.1425x; 1.1425x over previous
#include <cuda_runtime.h>
#include <math.h>

// ============================================================================
// ExponentialConcordanceLoss, O(N), ZERO cross-CTA communication.
//
// loss = ( sum_{i,j: t[j]<t[i], e[j], finite both} exp(s[i]-s[j]) ) / max(cnt,1)
//   a[i]  = finite[i] ? exp(s[i]) : 0
//   b0[j] = (finite[j] && e[j]) ? exp(-s[j]) : 0
//   total = sum_i a[i] * ( prefB0[bucket(i)] + same-bucket strict compares )
//
// Each of 8 plain blocks redundantly builds the FULL bucket structure in its
// OWN shared memory (redundant parallel work beats serialized cross-CTA
// round trips -- lesson from R5/R6):
//   1. read ALL preds/targets (L2-multicast); per-element t/b0/event kept in
//      registers (constant-index unrolled arrays); block min/max of finite t.
//   2. local event histogram (SMEM atomics over 1024 buckets).
//   3. local exclusive scan (1 bucket/thread, shuffle scan).
//   4. local scatter of (t_j, b0_j) event records into SMEM sorted array.
//   5. gather for this block's own 1024 elements only: prefix + short exact
//      same-bucket loop from SMEM (strict <, excludes ties/self).
//   6. block reduce; ticket: LAST block sums 8 partials in fixed order
//      (deterministic) and writes out.
// All phase ordering is __syncthreads(). Only global scratch: 8 partials +
// ticket. Counts int32 end-to-end (max 8192^2 < 2^31).
// ============================================================================

#define NMAX     8192
#define KB       1024
#define NCTAS    8
#define NTHREADS 1024
#define EPT      (NMAX / NTHREADS)     // 8 elements per thread

__device__ float    g_blockSum[NCTAS];
__device__ int      g_blockCnt[NCTAS];
__device__ unsigned g_ticket;          // zero at load; reset by last block

// Dynamic SMEM layout:
//   s_rec  : NMAX  float2  = 65536 B   (bucket-sorted event records)
//   s_hCnt : KB    int     =  4096 B
//   s_hB0  : KB    float   =  4096 B
//   s_pB0  : KB    float   =  4096 B
//   s_st   : KB+1  int     =  4100 B
#define SMEM_BYTES (NMAX * 8 + KB * 4 * 4 + 4)

extern __shared__ unsigned char smem_raw[];

__global__ void __launch_bounds__(NTHREADS, 1)
fused_local(const float* __restrict__ preds,
            const float* __restrict__ targets,
            float* __restrict__ out, int n) {
    float2* s_rec  = (float2*)smem_raw;
    int*    s_hCnt = (int*)(s_rec + NMAX);
    float*  s_hB0  = (float*)(s_hCnt + KB);
    float*  s_pB0  = (float*)(s_hB0 + KB);
    int*    s_st   = (int*)(s_pB0 + KB);   // KB+1 entries

    __shared__ float sWmn[32], sWmx[32];
    __shared__ float sWsum[32];
    __shared__ int   sWcnt[32];
    __shared__ float sScale[2];            // [0]=tmin, [1]=scale
    __shared__ float sScanB[33];
    __shared__ int   sScanN[33];

    const int tid  = threadIdx.x;
    const int cta  = blockIdx.x;
    const int lane = tid & 31;
    const int warp = tid >> 5;

    // ---- zero local histogram (1 bucket per thread) ------------------------
    s_hCnt[tid] = 0;
    s_hB0[tid]  = 0.0f;

    // ---- Phase 1: read ALL data; per-element prep in registers -------------
    float tArr[EPT], b0Arr[EPT];
    int   eMask = 0;
    float my_s = 0.0f, my_t = 0.0f;
    bool  my_fin = false;
    float tmn = __int_as_float(0x7f800000);     // +inf
    float tmx = __int_as_float(0xff800000);     // -inf
#pragma unroll
    for (int u = 0; u < EPT; u++) {
        int idx = u * NTHREADS + tid;
        float  sv = 0.0f;
        float2 tg = make_float2(__int_as_float(0x7fc00000), 0.0f);  // qNaN
        if (idx < n) {
            sv = __ldg(&preds[idx]);
            tg = __ldg(&((const float2*)targets)[idx]);
        }
        bool fin = isfinite(tg.x) && isfinite(sv);
        bool e   = fin && (tg.y != 0.0f);
        tArr[u]  = tg.x;
        b0Arr[u] = e ? __expf(-sv) : 0.0f;
        if (e) eMask |= (1 << u);
        if (fin) { tmn = fminf(tmn, tg.x); tmx = fmaxf(tmx, tg.x); }
        if (u == cta) { my_s = sv; my_t = tg.x; my_fin = fin; }
    }
#pragma unroll
    for (int o = 16; o > 0; o >>= 1) {
        tmn = fminf(tmn, __shfl_xor_sync(0xffffffffu, tmn, o));
        tmx = fmaxf(tmx, __shfl_xor_sync(0xffffffffu, tmx, o));
    }
    if (lane == 0) { sWmn[warp] = tmn; sWmx[warp] = tmx; }
    __syncthreads();
    if (warp == 0) {
        float a2 = sWmn[lane], b2 = sWmx[lane];
#pragma unroll
        for (int o = 16; o > 0; o >>= 1) {
            a2 = fminf(a2, __shfl_xor_sync(0xffffffffu, a2, o));
            b2 = fmaxf(b2, __shfl_xor_sync(0xffffffffu, b2, o));
        }
        if (lane == 0) {
            float range = b2 - a2;
            sScale[0] = a2;
            sScale[1] = (range > 0.0f) ? ((float)KB / range) : 0.0f;
        }
    }
    __syncthreads();

    // ---- Phase 2: local event histogram (SMEM atomics) ---------------------
    float tmin  = sScale[0];
    float scale = sScale[1];
    int bktArr[EPT], posArr[EPT];
    int my_bkt = 0;
#pragma unroll
    for (int u = 0; u < EPT; u++) {
        float x = (tArr[u] - tmin) * scale;     // NaN -> 0 after cvt; clamped
        int b = (int)x;
        b = max(0, min(KB - 1, b));
        bktArr[u] = b;
        if (u == cta) my_bkt = b;
        if (eMask & (1 << u)) {
            posArr[u] = atomicAdd(&s_hCnt[b], 1);
            atomicAdd(&s_hB0[b], b0Arr[u]);
        }
    }
    __syncthreads();

    // ---- Phase 3: local exclusive scan (1 bucket / thread) -----------------
    {
        float hb = s_hB0[tid];
        int   hn = s_hCnt[tid];
        float rb = hb; int rn = hn;
#pragma unroll
        for (int o = 1; o < 32; o <<= 1) {
            float vb = __shfl_up_sync(0xffffffffu, rb, o);
            int   vn = __shfl_up_sync(0xffffffffu, rn, o);
            if (lane >= o) { rb += vb; rn += vn; }
        }
        if (lane == 31) { sScanB[warp] = rb; sScanN[warp] = rn; }
        __syncthreads();
        if (warp == 0) {
            float wb = sScanB[lane]; int wn = sScanN[lane];
#pragma unroll
            for (int o = 1; o < 32; o <<= 1) {
                float vb = __shfl_up_sync(0xffffffffu, wb, o);
                int   vn = __shfl_up_sync(0xffffffffu, wn, o);
                if (lane >= o) { wb += vb; wn += vn; }
            }
            sScanB[lane + 1] = wb; sScanN[lane + 1] = wn;
            if (lane == 0) { sScanB[0] = 0.0f; sScanN[0] = 0; }
        }
        __syncthreads();
        float ib  = sScanB[warp] + rb;          // inclusive
        int   in2 = sScanN[warp] + rn;
        s_pB0[tid] = ib - hb;                   // exclusive
        s_st[tid]  = in2 - hn;
        if (tid == KB - 1) s_st[KB] = in2;
    }
    __syncthreads();

    // ---- Phase 4: local scatter of event records ----------------------------
#pragma unroll
    for (int u = 0; u < EPT; u++) {
        if (eMask & (1 << u)) {
            s_rec[s_st[bktArr[u]] + posArr[u]] = make_float2(tArr[u], b0Arr[u]);
        }
    }
    __syncthreads();

    // ---- Phase 5: gather for this block's own element -----------------------
    float ts = 0.0f;
    int   tc = 0;
    if (my_fin) {
        float S  = s_pB0[my_bkt];
        int   st = s_st[my_bkt];
        int   en = s_st[my_bkt + 1];
        int   C  = st;
        for (int m = st; m < en; m++) {
            float2 r = s_rec[m];
            if (r.x < my_t) { S += r.y; C += 1; }   // strict: drops ties/self
        }
        ts = __expf(my_s) * S;
        tc = C;
    }

    // ---- Phase 6: block reduce + ticket final reduce ------------------------
#pragma unroll
    for (int o = 16; o > 0; o >>= 1) {
        ts += __shfl_xor_sync(0xffffffffu, ts, o);
        tc += __shfl_xor_sync(0xffffffffu, tc, o);
    }
    if (lane == 0) { sWsum[warp] = ts; sWcnt[warp] = tc; }
    __syncthreads();
    if (warp == 0) {
        float s2 = sWsum[lane];
        int   c2 = sWcnt[lane];
#pragma unroll
        for (int o = 16; o > 0; o >>= 1) {
            s2 += __shfl_xor_sync(0xffffffffu, s2, o);
            c2 += __shfl_xor_sync(0xffffffffu, c2, o);
        }
        if (lane == 0) { g_blockSum[cta] = s2; g_blockCnt[cta] = c2; }
    }
    __syncthreads();

    if (tid == 0) {
        __threadfence();
        unsigned tkt = atomicAdd(&g_ticket, 1u);
        if (tkt == NCTAS - 1) {                 // last block finalizes
            __threadfence();
            float     s3 = 0.0f;
            long long c3 = 0;
#pragma unroll
            for (int b = 0; b < NCTAS; b++) {
                s3 += __ldcg(&g_blockSum[b]);
                c3 += (long long)__ldcg(&g_blockCnt[b]);
            }
            out[0] = s3 / fmaxf((float)c3, 1.0f);
            atomicExch(&g_ticket, 0u);          // reset for next replay
        }
    }
}

// ---------------------------------------------------------------------------
extern "C" void kernel_launch(void* const* d_in, const int* in_sizes, int n_in,
                              void* d_out, int out_size) {
    const float* preds   = (const float*)d_in[0];
    const float* targets = (const float*)d_in[1];
    int n = in_sizes[0];
    if (n > NMAX) n = NMAX;

    // Idempotent; needed for >48KB dynamic smem. Safe under graph capture.
    cudaFuncSetAttribute(fused_local, cudaFuncAttributeMaxDynamicSharedMemorySize,
                         SMEM_BYTES);

    fused_local<<<NCTAS, NTHREADS, SMEM_BYTES>>>(preds, targets, (float*)d_out, n);
}